// round 3
// baseline (speedup 1.0000x reference)
#include <cuda_runtime.h>

#define N 512
#define D 128
#define NV4 (D/4)          // 32 float4 per row
#define MARGIN 0.3f
#define THREADS 256
#define NWARPS (THREADS/32)

// Per-anchor partial results (no atomics needed; finalize kernel reduces).
__device__ double g_psum[N];
__device__ int    g_pcnt[N];

__global__ __launch_bounds__(THREADS)
void triplet_anchor_kernel(const float* __restrict__ X,
                           const int* __restrict__ labels) {
    const int i    = blockIdx.x;
    const int tid  = threadIdx.x;
    const int lane = tid & 31;
    const int warp = tid >> 5;

    __shared__ float d_row[N];     // distances from anchor i to all j
    __shared__ float posA[N];      // d[i,j] + margin for positive j
    __shared__ int   npos;
    __shared__ float wsum[NWARPS];
    __shared__ int   wcnt[NWARPS];

    if (tid == 0) npos = 0;

    // ---- Phase 1: distance row. One warp per j: each lane holds one float4
    // chunk of both rows; full row = exactly one coalesced LDG.128 per warp.
    const float4* __restrict__ X4 = (const float4*)X;
    const float4 xi = X4[i * NV4 + lane];

    #pragma unroll 4
    for (int j = warp; j < N; j += NWARPS) {
        const float4 xj = X4[j * NV4 + lane];
        float dx = xi.x - xj.x;
        float dy = xi.y - xj.y;
        float dz = xi.z - xj.z;
        float dw = xi.w - xj.w;
        float s = dx*dx + dy*dy + dz*dz + dw*dw;
        #pragma unroll
        for (int o = 16; o > 0; o >>= 1)
            s += __shfl_xor_sync(0xffffffffu, s, o);
        if (lane == 0)
            d_row[j] = (s > 0.0f) ? sqrtf(s) : 0.0f;
    }
    __syncthreads();

    // ---- Phase 2: gather positives (same label, j != i).
    const int li = labels[i];
    for (int j = tid; j < N; j += THREADS) {
        if (labels[j] == li && j != i) {
            int p = atomicAdd(&npos, 1);
            posA[p] = d_row[j] + MARGIN;
        }
    }
    __syncthreads();

    // ---- Phase 3: masked triplet sum. Negatives: labels[k] != li
    // (this also excludes k==i and k==j automatically).
    const int np = npos;
    float lsum = 0.0f;
    int   lcnt = 0;
    for (int k = tid; k < N; k += THREADS) {
        if (labels[k] != li) {
            const float b = d_row[k];
            for (int p = 0; p < np; p++) {
                const float v = posA[p] - b;   // d_ij + m - d_ik
                if (v > 0.0f)    lsum += v;
                if (v > 1e-16f)  lcnt += 1;
            }
        }
    }

    // ---- Block reduce
    #pragma unroll
    for (int o = 16; o > 0; o >>= 1) {
        lsum += __shfl_xor_sync(0xffffffffu, lsum, o);
        lcnt += __shfl_xor_sync(0xffffffffu, lcnt, o);
    }
    if (lane == 0) { wsum[warp] = lsum; wcnt[warp] = lcnt; }
    __syncthreads();
    if (tid == 0) {
        float s = 0.0f; int c = 0;
        #pragma unroll
        for (int w = 0; w < NWARPS; w++) { s += wsum[w]; c += wcnt[w]; }
        g_psum[i] = (double)s;
        g_pcnt[i] = c;
    }
}

__global__ void finalize_kernel(float* __restrict__ out) {
    __shared__ double ssum[N];
    __shared__ long long scnt[N];
    const int tid = threadIdx.x;
    ssum[tid] = g_psum[tid];
    scnt[tid] = (long long)g_pcnt[tid];
    __syncthreads();
    #pragma unroll
    for (int s = N / 2; s > 0; s >>= 1) {
        if (tid < s) { ssum[tid] += ssum[tid + s]; scnt[tid] += scnt[tid + s]; }
        __syncthreads();
    }
    if (tid == 0)
        out[0] = (float)(ssum[0] / ((double)scnt[0] + 1e-16));
}

extern "C" void kernel_launch(void* const* d_in, const int* in_sizes, int n_in,
                              void* d_out, int out_size) {
    const float* X      = (const float*)d_in[0];   // [512, 128] fp32
    const int*   labels = (const int*)d_in[1];     // [512] int32
    float*       out    = (float*)d_out;           // scalar

    triplet_anchor_kernel<<<N, THREADS>>>(X, labels);
    finalize_kernel<<<1, N>>>(out);
}

// round 4
// speedup vs baseline: 3.0250x; 3.0250x over previous
#include <cuda_runtime.h>

#define N 512
#define D 128
#define MARGIN 0.3f
#define TS 32           // distance tile size
#define KS 130          // padded smem row stride (even -> float2 conflict-free)
#define NWARPS 8

__device__ float               g_D[N * N];   // pairwise distances
__device__ double              g_sum  = 0.0;
__device__ int                 g_cnt  = 0;
__device__ unsigned int        g_done = 0u;

// ---------------------------------------------------------------------------
// K1: pairwise Euclidean distances, triangular tiles + mirror store.
// 136 blocks x 256 threads, 2x2 micro-tile, direct (a-b)^2 accumulation
// (no norm-trick cancellation).
// ---------------------------------------------------------------------------
__global__ __launch_bounds__(256)
void dist_kernel(const float* __restrict__ X) {
    const int b = blockIdx.x;
    // map linear block -> lower-triangular tile (ti >= tj)
    int ti = (int)((sqrtf(8.0f * (float)b + 1.0f) - 1.0f) * 0.5f);
    while ((ti + 1) * (ti + 2) / 2 <= b) ti++;
    while (ti * (ti + 1) / 2 > b) ti--;
    const int tj = b - ti * (ti + 1) / 2;
    const int i0 = ti * TS, j0 = tj * TS;

    __shared__ __align__(16) float As[TS * KS];
    __shared__ __align__(16) float Bs[TS * KS];

    const int tid = threadIdx.x;

    // Stage tiles: 32 rows x 128 floats each, lane-consecutive -> coalesced LDG,
    // consecutive-bank STS.
    #pragma unroll
    for (int v = 0; v < 16; v++) {
        const int idx = tid + v * 256;        // 0..4095
        const int r = idx >> 7, c = idx & 127;
        As[r * KS + c] = X[(i0 + r) * D + c];
        Bs[r * KS + c] = X[(j0 + r) * D + c];
    }
    __syncthreads();

    const int tx = tid & 15, ty = tid >> 4;
    const float* a0p = &As[ty * KS];
    const float* a1p = &As[(ty + 16) * KS];
    const float* b0p = &Bs[tx * KS];
    const float* b1p = &Bs[(tx + 16) * KS];

    float c00 = 0.f, c01 = 0.f, c10 = 0.f, c11 = 0.f;
    #pragma unroll 8
    for (int k = 0; k < D; k += 2) {
        const float2 a0 = *(const float2*)(a0p + k);
        const float2 a1 = *(const float2*)(a1p + k);
        const float2 b0 = *(const float2*)(b0p + k);
        const float2 b1 = *(const float2*)(b1p + k);
        float d;
        d = a0.x - b0.x; c00 += d * d;   d = a0.y - b0.y; c00 += d * d;
        d = a0.x - b1.x; c01 += d * d;   d = a0.y - b1.y; c01 += d * d;
        d = a1.x - b0.x; c10 += d * d;   d = a1.y - b0.y; c10 += d * d;
        d = a1.x - b1.x; c11 += d * d;   d = a1.y - b1.y; c11 += d * d;
    }

    const float d00 = sqrtf(c00), d01 = sqrtf(c01);
    const float d10 = sqrtf(c10), d11 = sqrtf(c11);
    const int gi0 = i0 + ty, gi1 = i0 + ty + 16;
    const int gj0 = j0 + tx, gj1 = j0 + tx + 16;

    g_D[gi0 * N + gj0] = d00;
    g_D[gi0 * N + gj1] = d01;
    g_D[gi1 * N + gj0] = d10;
    g_D[gi1 * N + gj1] = d11;
    if (ti != tj) {       // mirror into the upper triangle
        g_D[gj0 * N + gi0] = d00;
        g_D[gj1 * N + gi0] = d01;
        g_D[gj0 * N + gi1] = d10;
        g_D[gj1 * N + gi1] = d11;
    }
}

// ---------------------------------------------------------------------------
// K2: per-anchor masked triplet sum + fused finalize (atomic ticket).
// 512 blocks x 256 threads; all blocks co-resident -> one latency-overlapped wave.
// ---------------------------------------------------------------------------
__global__ __launch_bounds__(256)
void triplet_kernel(const int* __restrict__ labels, float* __restrict__ out) {
    const int i    = blockIdx.x;
    const int tid  = threadIdx.x;
    const int lane = tid & 31;
    const int warp = tid >> 5;

    __shared__ float d_row[N];
    __shared__ float posA[N];
    __shared__ int   slbl[N];
    __shared__ int   npos;
    __shared__ float wsum[NWARPS];
    __shared__ int   wcnt[NWARPS];

    if (tid == 0) npos = 0;

    #pragma unroll
    for (int j = tid; j < N; j += 256) {
        d_row[j] = g_D[i * N + j];
        slbl[j]  = labels[j];
    }
    __syncthreads();

    const int li = slbl[i];
    for (int j = tid; j < N; j += 256) {
        if (slbl[j] == li && j != i) {
            const int p = atomicAdd(&npos, 1);
            posA[p] = d_row[j] + MARGIN;   // d(anchor,pos) + margin
        }
    }
    __syncthreads();

    const int np = npos;
    float lsum = 0.0f;
    int   lcnt = 0;
    #pragma unroll
    for (int k = tid; k < N; k += 256) {
        if (slbl[k] != li) {               // negative (also excludes k==i, k==j)
            const float bneg = d_row[k];
            for (int p = 0; p < np; p++) {
                const float v = posA[p] - bneg;
                if (v > 0.0f)    lsum += v;
                if (v > 1e-16f)  lcnt += 1;
            }
        }
    }

    #pragma unroll
    for (int o = 16; o > 0; o >>= 1) {
        lsum += __shfl_xor_sync(0xffffffffu, lsum, o);
        lcnt += __shfl_xor_sync(0xffffffffu, lcnt, o);
    }
    if (lane == 0) { wsum[warp] = lsum; wcnt[warp] = lcnt; }
    __syncthreads();

    if (tid == 0) {
        float s = 0.0f; int c = 0;
        #pragma unroll
        for (int w = 0; w < NWARPS; w++) { s += wsum[w]; c += wcnt[w]; }
        atomicAdd(&g_sum, (double)s);
        atomicAdd(&g_cnt, c);
        __threadfence();
        const unsigned int ticket = atomicAdd(&g_done, 1u);
        if (ticket == (unsigned int)(N - 1)) {
            // last block: all partials are in L2 (atomics are L2-coherent);
            // read via atomics to stay off L1.
            const double S = atomicAdd(&g_sum, 0.0);
            const int    C = atomicAdd(&g_cnt, 0);
            out[0] = (float)(S / ((double)C + 1e-16));
            // reset for the next graph replay
            g_sum  = 0.0;
            g_cnt  = 0;
            g_done = 0u;
        }
    }
}

extern "C" void kernel_launch(void* const* d_in, const int* in_sizes, int n_in,
                              void* d_out, int out_size) {
    const float* X      = (const float*)d_in[0];   // [512, 128] fp32
    const int*   labels = (const int*)d_in[1];     // [512] int32
    float*       out    = (float*)d_out;           // scalar fp32

    const int ntiles = (N / TS) * (N / TS + 1) / 2;   // 136
    dist_kernel<<<ntiles, 256>>>(X);
    triplet_kernel<<<N, 256>>>(labels, out);
}